// round 14
// baseline (speedup 1.0000x reference)
#include <cuda_runtime.h>
#include <cstdint>

#define VOCAB 4096
#define HID   512
#define BATCH 64
#define TT    512

typedef unsigned long long ull;

// Scratch (static device arrays — allocation rules):
//   g_H   : [B,T,H] hidden states, tf32-rounded bits, k-permuted within 8-groups
//   g_WT  : transposed W_ih (embedding gather), L2-resident
//   g_Wtf : W_fc pre-rounded to tf32 bits, k-permuted within 8-groups
// All three are fully rewritten from the immutable inputs every call ->
// graph-replay deterministic. k-permutation (logical l -> physical p in each
// group of 8): p = l<4 ? 2l : 2(l-4)+1. Applied identically to both GEMM
// operands -> dot products unchanged, but mma fragment pairs (tg, tg+4)
// become physically adjacent -> LDS.64 fragment loads.
__device__ float g_H  [(size_t)BATCH * TT * HID];   // 64 MB
__device__ float g_WT [(size_t)VOCAB * HID];        // 8 MB
__device__ float g_Wtf[(size_t)VOCAB * HID];        // 8 MB

__device__ __forceinline__ uint32_t smem_u32(const void* p) {
    return (uint32_t)__cvta_generic_to_shared(p);
}

// Packed dual-FMA: d.f32x2 += a.f32x2 * b.f32x2  (FFMA2; PTX-only per SASS_QUICKREF)
__device__ __forceinline__ void ffma2(ull& d, ull a, ull b) {
    asm("fma.rn.f32x2 %0, %1, %2, %0;" : "+l"(d) : "l"(a), "l"(b));
}

__device__ __forceinline__ uint32_t f2tf32(float f) {
    uint32_t o;
    asm("cvt.rna.tf32.f32 %0, %1;" : "=r"(o) : "f"(f));
    return o;
}

// cp.async 16B GMEM -> SMEM (LDGSTS), L2-only path. .cg is 16B-only (our only
// size); all src/dst addresses are 16B-aligned by construction.
#define CP_ASYNC16(saddr, gptr) \
    asm volatile("cp.async.cg.shared.global [%0], [%1], 16;" \
                 :: "r"(saddr), "l"(gptr) : "memory")
#define CP_COMMIT()  asm volatile("cp.async.commit_group;" ::: "memory")
#define CP_WAIT(n)   asm volatile("cp.async.wait_group %0;" :: "n"(n) : "memory")

// ============================================================================
// W_ih transpose: g_WT[v][h] = W_ih[h][v]  (8 MB, once per launch)
// ============================================================================
__global__ void transpose_wih(const float* __restrict__ W) {
    __shared__ float tile[32][33];
    int vx = blockIdx.x * 32 + threadIdx.x;
    int hy = blockIdx.y * 32 + threadIdx.y;
    #pragma unroll
    for (int r = 0; r < 32; r += 8)
        tile[threadIdx.y + r][threadIdx.x] = W[(size_t)(hy + r) * VOCAB + vx];
    __syncthreads();
    int vo = blockIdx.x * 32 + threadIdx.y;
    int ho = blockIdx.y * 32 + threadIdx.x;
    #pragma unroll
    for (int r = 0; r < 32; r += 8)
        g_WT[(size_t)(vo + r) * HID + ho] = tile[threadIdx.x][threadIdx.y + r];
}

// ============================================================================
// W_fc -> tf32 bits, k-permuted within each 8-group. Thread handles one group
// (8 floats, same 32B sector in and out -> coalescing preserved).
// physical layout of a group: [l0 l4 l1 l5 | l2 l6 l3 l7]
// ============================================================================
__global__ void wfc_to_tf32(const float* __restrict__ Wfc) {
    size_t i = (size_t)blockIdx.x * blockDim.x + threadIdx.x;  // group index
    float4 v0 = *(const float4*)&Wfc[i * 8];      // l0 l1 l2 l3
    float4 v1 = *(const float4*)&Wfc[i * 8 + 4];  // l4 l5 l6 l7
    float4 o0, o1;
    o0.x = __uint_as_float(f2tf32(v0.x));  // l0
    o0.y = __uint_as_float(f2tf32(v1.x));  // l4
    o0.z = __uint_as_float(f2tf32(v0.y));  // l1
    o0.w = __uint_as_float(f2tf32(v1.y));  // l5
    o1.x = __uint_as_float(f2tf32(v0.z));  // l2
    o1.y = __uint_as_float(f2tf32(v1.z));  // l6
    o1.z = __uint_as_float(f2tf32(v0.w));  // l3
    o1.w = __uint_as_float(f2tf32(v1.w));  // l7
    *(float4*)&g_Wtf[i * 8]     = o0;
    *(float4*)&g_Wtf[i * 8 + 4] = o1;
}

// ============================================================================
// RNN: 16 clusters x 8 CTAs (128 SMs; placement check: ~70/78 SMs per die ->
// floor(70/8)+floor(78/8) = 17 >= 16 clusters fit -> ONE wave). Cluster owns
// 4 batches. CTA rank r owns j-rows [64r, 64r+64); W_hh slice in REGISTERS:
// warp -> 8 rows, lane -> k in {4*lane + 128i + j} (W[8][4] ulonglong2 = 128
// regs, loaded once). Per step: h via conflict-free LDS.128; FFMA2 dot
// products; halving butterfly (lane l owns output ji=l>>2, b=l&3); tanh;
// DSMEM push to 8 CTAs; arrive (RELEASE for the pushes, per PTX
// barrier.cluster semantics) BEFORE the g_H store so the store issue cost
// overlaps the arrive->wait window; wait (ACQUIRE).
// Race-freedom: within step t, reads of buf (t&1) precede the arrive; writes
// of buf (t&1) at step t+1 follow the wait -> one barrier per step suffices.
// Compile-time __cluster_dims__ + plain <<< >>> launch is graph-capturable.
// ============================================================================
__global__ void __launch_bounds__(256, 1) __cluster_dims__(8, 1, 1)
rnn_kernel(const int* __restrict__ input, const float* __restrict__ h0,
           const float* __restrict__ W_hh, const float* __restrict__ b_ih,
           const float* __restrict__ b_hh)
{
    __shared__ float hb[2][4][HID];    // double-buffered h, 16 KB

    const int tid  = threadIdx.x;
    const int lane = tid & 31, warp = tid >> 5;
    const int rank = blockIdx.x & 7;
    const int cid  = blockIdx.x >> 3;
    const int j0   = rank * 64 + warp * 8;

    // W_hh slice -> registers (step-invariant). 4*lane floats = 16B aligned.
    ulonglong2 w2[8][4];
    #pragma unroll
    for (int ji = 0; ji < 8; ji++)
        #pragma unroll
        for (int i = 0; i < 4; i++)
            w2[ji][i] = *(const ulonglong2*)
                &W_hh[(size_t)(j0 + ji) * HID + 4 * lane + 128 * i];

    // Stage h0 into buffer 0 (every CTA holds all 4 of its cluster's batches).
    for (int i = tid; i < 4 * 128; i += 256) {
        int b = i >> 7, c = i & 127;
        *(float4*)&hb[0][b][c * 4] =
            *(const float4*)&h0[(size_t)(cid * 4 + b) * HID + c * 4];
    }

    // Output ownership after reduction: lane l -> (ji = l>>2, b = l&3).
    const int o_ji  = lane >> 2, o_b = lane & 3;
    const int jg    = j0 + o_ji;
    const int bglob = cid * 4 + o_b;
    const float bsum = b_ih[jg] + b_hh[jg];

    // g_H column: k-permuted within the 8-group (matches proj/Wtf layout).
    const int jl = jg & 7;
    const int pj = (jg & ~7) | ((jl < 4) ? (2 * jl) : (2 * (jl - 4) + 1));

    // Precompute peer DSMEM addresses for this thread's output slot (buffer 0).
    uint32_t paddr[8];
    {
        uint32_t laddr = smem_u32(&hb[0][o_b][jg]);
        #pragma unroll
        for (int r = 0; r < 8; r++)
            asm("mapa.shared::cluster.u32 %0, %1, %2;"
                : "=r"(paddr[r]) : "r"(laddr), "r"(r));
    }

    // Bumped pointers: no per-step 64-bit index math in the hot loop.
    const int* inp  = &input[bglob * TT];
    float*     hout = &g_H[((size_t)bglob * TT) * HID + pj];

    asm volatile("barrier.cluster.arrive.aligned;" ::: "memory");
    asm volatile("barrier.cluster.wait.aligned;"   ::: "memory");

    int cur = 0;
    #pragma unroll 1
    for (int t = 0; t < TT; t++) {
        // Embedding gather for the owned output — issued early, hides under FMAs.
        int   tok = __ldg(inp + t);
        float xw  = __ldg(&g_WT[(size_t)tok * HID + jg]);

        // Dot products: per batch, 8 packed accumulators (kept small -> no
        // spill), collapsed to scalar partials s[0..31] immediately.
        float s[32];
        #pragma unroll
        for (int b = 0; b < 4; b++) {
            const ulonglong2* hp = (const ulonglong2*)&hb[cur][b][0];
            ulonglong2 h2[4];
            #pragma unroll
            for (int i = 0; i < 4; i++) h2[i] = hp[lane + 32 * i];  // LDS.128, conflict-free
            ull a8[8];
            #pragma unroll
            for (int ji = 0; ji < 8; ji++) a8[ji] = 0ull;
            #pragma unroll
            for (int ji = 0; ji < 8; ji++)
                #pragma unroll
                for (int i = 0; i < 4; i++) {
                    ffma2(a8[ji], w2[ji][i].x, h2[i].x);
                    ffma2(a8[ji], w2[ji][i].y, h2[i].y);
                }
            #pragma unroll
            for (int ji = 0; ji < 8; ji++) {
                float lo = __uint_as_float((uint32_t)a8[ji]);
                float hi = __uint_as_float((uint32_t)(a8[ji] >> 32));
                s[ji * 4 + b] = lo + hi;
            }
        }

        // Halving butterfly: 32 partial-sum sets over 32 lanes; lane l ends
        // holding the full k-reduction for output index l in s[0].
        #pragma unroll
        for (int m = 16; m >= 1; m >>= 1) {
            bool himask = (lane & m) != 0;
            #pragma unroll
            for (int o = 0; o < m; o++) {
                float send = himask ? s[o]     : s[o + m];
                float keep = himask ? s[o + m] : s[o];
                s[o] = keep + __shfl_xor_sync(0xffffffffu, send, m);
            }
        }

        float hv = tanhf(xw + bsum + s[0]);

        // Push full-precision h to all 8 CTAs' next buffer, then arrive
        // (release). The g_H store happens inside the arrive->wait window.
        int nxt = cur ^ 1;
        uint32_t boff = (uint32_t)nxt * (4 * HID * 4);   // 8192 B per buffer
        #pragma unroll
        for (int r = 0; r < 8; r++)
            asm volatile("st.shared::cluster.f32 [%0], %1;"
                         :: "r"(paddr[r] + boff), "f"(hv) : "memory");
        asm volatile("barrier.cluster.arrive.aligned;" ::: "memory");

        // Projection copy / h_last source: tf32-rounded (rel err <= 1.2e-4).
        *hout = __uint_as_float(f2tf32(hv));
        hout += HID;

        asm volatile("barrier.cluster.wait.aligned;"   ::: "memory");
        cur = nxt;
    }
}

// ============================================================================
// Projection: logits[32768,4096] = H @ W_fc^T + b_fc, tf32 mma.sync m16n8k8.
// Operands PRE-ROUNDED to tf32 and k-PERMUTED ([0,4,1,5,2,6,3,7] per 8-group)
// -> each fragment pair (tg, tg+4) is one LDS.64: 12 LDS issues/thread/kk
// instead of 24. PSTRIDE=40 (mod 32 = 8) -> LDS.64 banks 8g+2tg distinct per
// 16-lane phase -> conflict-free. cp.async double-buffering, no reg staging.
// ============================================================================
#define BM 128
#define BN 128
#define BK 32
#define PSTRIDE 40          // row stride 160 B
#define TILE_U32 (BM * PSTRIDE)
#define PROJ_SMEM (4 * TILE_U32 * (int)sizeof(uint32_t))   // 80 KB
#define GSTEP (32 * HID * 4)         // 65536 B: GMEM delta between reps
#define SSTEP (32 * PSTRIDE * 4)     // 5120  B: SMEM delta between reps

__device__ __forceinline__ void mma_tf32(float* c, const uint32_t* a, const uint32_t* bf) {
    asm volatile(
        "mma.sync.aligned.m16n8k8.row.col.f32.tf32.tf32.f32 "
        "{%0,%1,%2,%3}, {%4,%5,%6,%7}, {%8,%9}, {%0,%1,%2,%3};"
        : "+f"(c[0]), "+f"(c[1]), "+f"(c[2]), "+f"(c[3])
        : "r"(a[0]), "r"(a[1]), "r"(a[2]), "r"(a[3]), "r"(bf[0]), "r"(bf[1]));
}

__global__ void __launch_bounds__(256, 2)
proj_kernel(const float* __restrict__ bfc, float* __restrict__ outp)
{
    extern __shared__ uint32_t sm[];
    uint32_t* As = sm;                    // [2][TILE_U32]
    uint32_t* Bs = sm + 2 * TILE_U32;     // [2][TILE_U32]

    const int tid  = threadIdx.x;
    const int m0   = blockIdx.y * BM;
    const int n0   = blockIdx.x * BN;
    const int lane = tid & 31, warp = tid >> 5;
    const int wm = (warp & 1) * 64;
    const int wn = (warp >> 1) * 32;
    const int g  = lane >> 2, tg = lane & 3;

    // Staging slot rep=0: row = tid>>3, c4 = tid&7. Other reps at +rep*GSTEP /
    // +rep*SSTEP (compile-time immediates -> no extra live registers).
    const int row0 = tid >> 3, c40 = tid & 7;
    const char* gA = (const char*)&g_H  [((size_t)(m0 + row0)) * HID + c40 * 4];
    const char* gB = (const char*)&g_Wtf[((size_t)(n0 + row0)) * HID + c40 * 4];
    const uint32_t sA0 = smem_u32(&As[row0 * PSTRIDE + c40 * 4]);
    const uint32_t sB0 = smem_u32(&Bs[row0 * PSTRIDE + c40 * 4]);
    const uint32_t bufB = TILE_U32 * 4;   // byte offset of buffer 1

    float acc[4][4][4];
    #pragma unroll
    for (int mi = 0; mi < 4; mi++)
        #pragma unroll
        for (int ni = 0; ni < 4; ni++)
            #pragma unroll
            for (int q = 0; q < 4; q++) acc[mi][ni][q] = 0.f;

    // Prefetch tile 0 into buffer 0.
    #pragma unroll
    for (int rep = 0; rep < 4; rep++) {
        CP_ASYNC16(sA0 + rep * SSTEP, gA + rep * GSTEP);
        CP_ASYNC16(sB0 + rep * SSTEP, gB + rep * GSTEP);
    }
    CP_COMMIT();

    int buf = 0;
    const int NT = HID / BK;  // 16
    float bias0[4], bias1[4];
    #pragma unroll 1
    for (int kt = 0; kt < NT; kt++) {
        if (kt + 1 < NT) {
            uint32_t off = (buf ^ 1) ? bufB : 0u;
            const uint32_t kb = (uint32_t)(kt + 1) * BK * 4;  // byte advance
            #pragma unroll
            for (int rep = 0; rep < 4; rep++) {
                CP_ASYNC16(sA0 + off + rep * SSTEP, gA + kb + rep * GSTEP);
                CP_ASYNC16(sB0 + off + rep * SSTEP, gB + kb + rep * GSTEP);
            }
            CP_COMMIT();
            CP_WAIT(1);     // tile kt landed; tile kt+1 may be in flight
        } else {
            CP_WAIT(0);
            // Prefetch epilogue bias now: L2 latency overlaps the final
            // mma section + __syncthreads instead of serializing after it.
            #pragma unroll
            for (int ni = 0; ni < 4; ni++) {
                int col = n0 + wn + ni * 8 + 2 * tg;
                bias0[ni] = __ldg(&bfc[col]);
                bias1[ni] = __ldg(&bfc[col + 1]);
            }
        }
        __syncthreads();    // tile kt visible to all threads

        const uint32_t* Ab = As + buf * TILE_U32;
        const uint32_t* Bb = Bs + buf * TILE_U32;
        #pragma unroll
        for (int kk = 0; kk < BK; kk += 8) {
            // Permuted layout: physical (kk+2tg, kk+2tg+1) = logical (tg, tg+4).
            uint32_t a[4][4];
            #pragma unroll
            for (int mi = 0; mi < 4; mi++) {
                int r = wm + mi * 16 + g;
                uint2 lo = *(const uint2*)&Ab[r * PSTRIDE + kk + 2 * tg];
                uint2 hi = *(const uint2*)&Ab[(r + 8) * PSTRIDE + kk + 2 * tg];
                a[mi][0] = lo.x; a[mi][2] = lo.y;   // (r,   tg), (r,   tg+4)
                a[mi][1] = hi.x; a[mi][3] = hi.y;   // (r+8, tg), (r+8, tg+4)
            }
            uint32_t bf[4][2];
            #pragma unroll
            for (int ni = 0; ni < 4; ni++) {
                int n = wn + ni * 8 + g;
                uint2 bv = *(const uint2*)&Bb[n * PSTRIDE + kk + 2 * tg];
                bf[ni][0] = bv.x; bf[ni][1] = bv.y; // (n, tg), (n, tg+4)
            }
            #pragma unroll
            for (int mi = 0; mi < 4; mi++)
                #pragma unroll
                for (int ni = 0; ni < 4; ni++)
                    mma_tf32(acc[mi][ni], a[mi], bf[ni]);
        }
        if (kt + 1 < NT) __syncthreads();   // done reading buf before overwrite
        buf ^= 1;
    }

    // Epilogue: + bias (already in regs), float2 stores.
    #pragma unroll
    for (int ni = 0; ni < 4; ni++) {
        int col = n0 + wn + ni * 8 + 2 * tg;
        #pragma unroll
        for (int mi = 0; mi < 4; mi++) {
            int row = m0 + wm + mi * 16 + g;
            float2 v0 = make_float2(acc[mi][ni][0] + bias0[ni],
                                    acc[mi][ni][1] + bias1[ni]);
            float2 v1 = make_float2(acc[mi][ni][2] + bias0[ni],
                                    acc[mi][ni][3] + bias1[ni]);
            *(float2*)&outp[(size_t)row * VOCAB + col] = v0;
            *(float2*)&outp[(size_t)(row + 8) * VOCAB + col] = v1;
        }
    }
}

// ============================================================================
// h_last tail: H[b, T-1, :] -> end of d_out (un-permuting the k-groups).
// ============================================================================
__global__ void hlast_kernel(float* __restrict__ outp) {
    int i = blockIdx.x * blockDim.x + threadIdx.x;   // 0..32767
    int b = i >> 9, jj = i & 511;
    int l = jj & 7;
    int p = (l < 4) ? (2 * l) : (2 * (l - 4) + 1);
    outp[i] = g_H[((size_t)b * TT + (TT - 1)) * HID + (jj & ~7) + p];
}

extern "C" void kernel_launch(void* const* d_in, const int* in_sizes, int n_in,
                              void* d_out, int out_size) {
    const int*   input  = (const int*)d_in[0];
    const float* hidden = (const float*)d_in[1];
    const float* W_ih   = (const float*)d_in[2];
    const float* W_hh   = (const float*)d_in[3];
    const float* b_ih   = (const float*)d_in[4];
    const float* b_hh   = (const float*)d_in[5];
    const float* W_fc   = (const float*)d_in[6];
    const float* b_fc   = (const float*)d_in[7];
    float* outp = (float*)d_out;

    // Idempotent, immediate (not a stream op -> legal under graph capture).
    cudaFuncSetAttribute(proj_kernel,
                         cudaFuncAttributeMaxDynamicSharedMemorySize, PROJ_SMEM);

    transpose_wih<<<dim3(VOCAB / 32, HID / 32), dim3(32, 8)>>>(W_ih);
    wfc_to_tf32<<<(VOCAB * HID / 8) / 256, 256>>>(W_fc);

    rnn_kernel<<<128, 256>>>(input, hidden, W_hh, b_ih, b_hh);

    // h_last depends only on rnn; launch it ahead of the long projection.
    long long logits_elems = (long long)BATCH * TT * VOCAB;
    if ((long long)out_size >= logits_elems + (long long)BATCH * HID) {
        hlast_kernel<<<64, 512>>>(outp + (size_t)out_size - (size_t)BATCH * HID);
    }

    dim3 grid(VOCAB / BN, (BATCH * TT) / BM);   // n fastest -> W tiles L2-resident
    proj_kernel<<<grid, 256, PROJ_SMEM>>>(b_fc, outp);
}

// round 16
// speedup vs baseline: 1.0164x; 1.0164x over previous
#include <cuda_runtime.h>
#include <cstdint>

#define VOCAB 4096
#define HID   512
#define BATCH 64
#define TT    512

typedef unsigned long long ull;

// Scratch (static device arrays — allocation rules):
//   g_H   : [B,T,H] hidden states, tf32-rounded bits, k-permuted within 8-groups
//   g_WT  : transposed W_ih (embedding gather), L2-resident
//   g_Wtf : W_fc pre-rounded to tf32 bits, k-permuted within 8-groups
// All three fully rewritten from immutable inputs every call -> replay-deterministic.
// k-permutation (logical l -> physical p per 8-group): p = l<4 ? 2l : 2(l-4)+1,
// applied to BOTH GEMM operands -> dot products unchanged, mma fragment pairs
// (tg, tg+4) physically adjacent -> LDS.64 fragment loads.
__device__ float g_H  [(size_t)BATCH * TT * HID];   // 64 MB
__device__ float g_WT [(size_t)VOCAB * HID];        // 8 MB
__device__ float g_Wtf[(size_t)VOCAB * HID];        // 8 MB

__device__ __forceinline__ uint32_t smem_u32(const void* p) {
    return (uint32_t)__cvta_generic_to_shared(p);
}

// Packed dual-FMA: d.f32x2 += a.f32x2 * b.f32x2  (FFMA2; PTX-only per SASS_QUICKREF)
__device__ __forceinline__ void ffma2(ull& d, ull a, ull b) {
    asm("fma.rn.f32x2 %0, %1, %2, %0;" : "+l"(d) : "l"(a), "l"(b));
}

__device__ __forceinline__ uint32_t f2tf32(float f) {
    uint32_t o;
    asm("cvt.rna.tf32.f32 %0, %1;" : "=r"(o) : "f"(f));
    return o;
}

// cp.async 16B GMEM -> SMEM (LDGSTS); .cg is 16B-only, all addresses 16B-aligned.
#define CP_ASYNC16(saddr, gptr) \
    asm volatile("cp.async.cg.shared.global [%0], [%1], 16;" \
                 :: "r"(saddr), "l"(gptr) : "memory")
#define CP_COMMIT()  asm volatile("cp.async.commit_group;" ::: "memory")
#define CP_WAIT(n)   asm volatile("cp.async.wait_group %0;" :: "n"(n) : "memory")

// ============================================================================
// prep: z=0 -> W_ih transpose into g_WT; z=1 -> W_fc tf32+permute into g_Wtf.
// Merged into ONE kernel so the whole pipeline is 3 launches (attribution:
// fixed ncu capture slot then lands on proj_kernel).
// ============================================================================
__global__ void prep_kernel(const float* __restrict__ W_ih,
                            const float* __restrict__ W_fc) {
    if (blockIdx.z == 0) {
        // Transpose g_WT[v][h] = W_ih[h][v]
        __shared__ float tile[32][33];
        int vx = blockIdx.x * 32 + threadIdx.x;
        int hy = blockIdx.y * 32 + threadIdx.y;
        #pragma unroll
        for (int r = 0; r < 32; r += 8)
            tile[threadIdx.y + r][threadIdx.x] = W_ih[(size_t)(hy + r) * VOCAB + vx];
        __syncthreads();
        int vo = blockIdx.x * 32 + threadIdx.y;
        int ho = blockIdx.y * 32 + threadIdx.x;
        #pragma unroll
        for (int r = 0; r < 32; r += 8)
            g_WT[(size_t)(vo + r) * HID + ho] = tile[threadIdx.x][threadIdx.y + r];
    } else {
        // W_fc -> tf32 bits, k-permuted per 8-group: [l0 l4 l1 l5 | l2 l6 l3 l7]
        int bid = blockIdx.y * gridDim.x + blockIdx.x;          // 0..2047
        int tid = threadIdx.y * 32 + threadIdx.x;               // 0..255
        size_t i = (size_t)bid * 256 + tid;                     // group index
        if (i < (size_t)VOCAB * HID / 8) {
            float4 v0 = *(const float4*)&W_fc[i * 8];      // l0 l1 l2 l3
            float4 v1 = *(const float4*)&W_fc[i * 8 + 4];  // l4 l5 l6 l7
            float4 o0, o1;
            o0.x = __uint_as_float(f2tf32(v0.x));  // l0
            o0.y = __uint_as_float(f2tf32(v1.x));  // l4
            o0.z = __uint_as_float(f2tf32(v0.y));  // l1
            o0.w = __uint_as_float(f2tf32(v1.y));  // l5
            o1.x = __uint_as_float(f2tf32(v0.z));  // l2
            o1.y = __uint_as_float(f2tf32(v1.z));  // l6
            o1.z = __uint_as_float(f2tf32(v0.w));  // l3
            o1.w = __uint_as_float(f2tf32(v1.w));  // l7
            *(float4*)&g_Wtf[i * 8]     = o0;
            *(float4*)&g_Wtf[i * 8 + 4] = o1;
        }
    }
}

// ============================================================================
// RNN: 16 clusters x 8 CTAs (128 SMs, one wave; 17 clusters of 8 fit per-die).
// Cluster owns 4 batches; CTA rank r owns j-rows [64r, 64r+64); W_hh slice in
// REGISTERS (W[8][4] ulonglong2 = 128 regs, loaded once). Per step: h via
// conflict-free LDS.128; FFMA2 dot products; halving butterfly (lane l owns
// output ji=l>>2, b=l&3); tanh; DSMEM push to 8 CTAs; arrive (RELEASE) before
// the g_H store so its issue cost overlaps the arrive->wait window; wait
// (ACQUIRE). One barrier/step is race-free (buffer parity argument).
// h_last is folded in: at t==TT-1 each thread writes its full-fp32 output
// directly to the output tail (one unique slot per thread, 32768 total).
// ============================================================================
__global__ void __launch_bounds__(256, 1) __cluster_dims__(8, 1, 1)
rnn_kernel(const int* __restrict__ input, const float* __restrict__ h0,
           const float* __restrict__ W_hh, const float* __restrict__ b_ih,
           const float* __restrict__ b_hh, float* __restrict__ hlast_out)
{
    __shared__ float hb[2][4][HID];    // double-buffered h, 16 KB

    const int tid  = threadIdx.x;
    const int lane = tid & 31, warp = tid >> 5;
    const int rank = blockIdx.x & 7;
    const int cid  = blockIdx.x >> 3;
    const int j0   = rank * 64 + warp * 8;

    // W_hh slice -> registers (step-invariant). 4*lane floats = 16B aligned.
    ulonglong2 w2[8][4];
    #pragma unroll
    for (int ji = 0; ji < 8; ji++)
        #pragma unroll
        for (int i = 0; i < 4; i++)
            w2[ji][i] = *(const ulonglong2*)
                &W_hh[(size_t)(j0 + ji) * HID + 4 * lane + 128 * i];

    // Stage h0 into buffer 0 (every CTA holds all 4 of its cluster's batches).
    for (int i = tid; i < 4 * 128; i += 256) {
        int b = i >> 7, c = i & 127;
        *(float4*)&hb[0][b][c * 4] =
            *(const float4*)&h0[(size_t)(cid * 4 + b) * HID + c * 4];
    }

    // Output ownership after reduction: lane l -> (ji = l>>2, b = l&3).
    const int o_ji  = lane >> 2, o_b = lane & 3;
    const int jg    = j0 + o_ji;
    const int bglob = cid * 4 + o_b;
    const float bsum = b_ih[jg] + b_hh[jg];

    // g_H column: k-permuted within the 8-group (matches proj/Wtf layout).
    const int jl = jg & 7;
    const int pj = (jg & ~7) | ((jl < 4) ? (2 * jl) : (2 * (jl - 4) + 1));

    // Precompute peer DSMEM addresses for this thread's output slot (buffer 0).
    uint32_t paddr[8];
    {
        uint32_t laddr = smem_u32(&hb[0][o_b][jg]);
        #pragma unroll
        for (int r = 0; r < 8; r++)
            asm("mapa.shared::cluster.u32 %0, %1, %2;"
                : "=r"(paddr[r]) : "r"(laddr), "r"(r));
    }

    // Bumped pointers: no per-step 64-bit index math in the hot loop.
    const int* inp  = &input[bglob * TT];
    float*     hout = &g_H[((size_t)bglob * TT) * HID + pj];

    asm volatile("barrier.cluster.arrive.aligned;" ::: "memory");
    asm volatile("barrier.cluster.wait.aligned;"   ::: "memory");

    int cur = 0;
    #pragma unroll 1
    for (int t = 0; t < TT; t++) {
        // Embedding gather for the owned output — issued early, hides under FMAs.
        int   tok = __ldg(inp + t);
        float xw  = __ldg(&g_WT[(size_t)tok * HID + jg]);

        // Dot products: per batch, 8 packed accumulators (no spill), collapsed
        // to scalar partials s[0..31] immediately.
        float s[32];
        #pragma unroll
        for (int b = 0; b < 4; b++) {
            const ulonglong2* hp = (const ulonglong2*)&hb[cur][b][0];
            ulonglong2 h2[4];
            #pragma unroll
            for (int i = 0; i < 4; i++) h2[i] = hp[lane + 32 * i];  // LDS.128, conflict-free
            ull a8[8];
            #pragma unroll
            for (int ji = 0; ji < 8; ji++) a8[ji] = 0ull;
            #pragma unroll
            for (int ji = 0; ji < 8; ji++)
                #pragma unroll
                for (int i = 0; i < 4; i++) {
                    ffma2(a8[ji], w2[ji][i].x, h2[i].x);
                    ffma2(a8[ji], w2[ji][i].y, h2[i].y);
                }
            #pragma unroll
            for (int ji = 0; ji < 8; ji++) {
                float lo = __uint_as_float((uint32_t)a8[ji]);
                float hi = __uint_as_float((uint32_t)(a8[ji] >> 32));
                s[ji * 4 + b] = lo + hi;
            }
        }

        // Halving butterfly: lane l ends holding output index l in s[0].
        #pragma unroll
        for (int m = 16; m >= 1; m >>= 1) {
            bool himask = (lane & m) != 0;
            #pragma unroll
            for (int o = 0; o < m; o++) {
                float send = himask ? s[o]     : s[o + m];
                float keep = himask ? s[o + m] : s[o];
                s[o] = keep + __shfl_xor_sync(0xffffffffu, send, m);
            }
        }

        float hv = tanhf(xw + bsum + s[0]);

        // Push full-precision h to all 8 CTAs' next buffer, then arrive
        // (release). The g_H store happens inside the arrive->wait window.
        int nxt = cur ^ 1;
        uint32_t boff = (uint32_t)nxt * (4 * HID * 4);   // 8192 B per buffer
        #pragma unroll
        for (int r = 0; r < 8; r++)
            asm volatile("st.shared::cluster.f32 [%0], %1;"
                         :: "r"(paddr[r] + boff), "f"(hv) : "memory");
        asm volatile("barrier.cluster.arrive.aligned;" ::: "memory");

        // Projection copy: tf32-rounded (rel err <= 1.2e-4).
        *hout = __uint_as_float(f2tf32(hv));
        hout += HID;

        // Folded h_last: full-fp32 output, one unique slot per thread.
        if (t == TT - 1 && hlast_out)
            hlast_out[bglob * HID + jg] = hv;

        asm volatile("barrier.cluster.wait.aligned;"   ::: "memory");
        cur = nxt;
    }
}

// ============================================================================
// Projection: logits[32768,4096] = H @ W_fc^T + b_fc, tf32 mma.sync m16n8k8.
// Operands PRE-ROUNDED to tf32 and k-PERMUTED -> fragment pairs are LDS.64
// (12 LDS issues/thread/kk vs 24). PSTRIDE=40 -> conflict-free LDS.64.
// cp.async double-buffering, no register staging.
// ============================================================================
#define BM 128
#define BN 128
#define BK 32
#define PSTRIDE 40          // row stride 160 B
#define TILE_U32 (BM * PSTRIDE)
#define PROJ_SMEM (4 * TILE_U32 * (int)sizeof(uint32_t))   // 80 KB
#define GSTEP (32 * HID * 4)         // 65536 B: GMEM delta between reps
#define SSTEP (32 * PSTRIDE * 4)     // 5120  B: SMEM delta between reps

__device__ __forceinline__ void mma_tf32(float* c, const uint32_t* a, const uint32_t* bf) {
    asm volatile(
        "mma.sync.aligned.m16n8k8.row.col.f32.tf32.tf32.f32 "
        "{%0,%1,%2,%3}, {%4,%5,%6,%7}, {%8,%9}, {%0,%1,%2,%3};"
        : "+f"(c[0]), "+f"(c[1]), "+f"(c[2]), "+f"(c[3])
        : "r"(a[0]), "r"(a[1]), "r"(a[2]), "r"(a[3]), "r"(bf[0]), "r"(bf[1]));
}

__global__ void __launch_bounds__(256, 2)
proj_kernel(const float* __restrict__ bfc, float* __restrict__ outp)
{
    extern __shared__ uint32_t sm[];
    uint32_t* As = sm;                    // [2][TILE_U32]
    uint32_t* Bs = sm + 2 * TILE_U32;     // [2][TILE_U32]

    const int tid  = threadIdx.x;
    const int m0   = blockIdx.y * BM;
    const int n0   = blockIdx.x * BN;
    const int lane = tid & 31, warp = tid >> 5;
    const int wm = (warp & 1) * 64;
    const int wn = (warp >> 1) * 32;
    const int g  = lane >> 2, tg = lane & 3;

    // Staging slot rep=0: row = tid>>3, c4 = tid&7; reps at +rep*GSTEP/SSTEP
    // (compile-time immediates -> no extra live registers).
    const int row0 = tid >> 3, c40 = tid & 7;
    const char* gA = (const char*)&g_H  [((size_t)(m0 + row0)) * HID + c40 * 4];
    const char* gB = (const char*)&g_Wtf[((size_t)(n0 + row0)) * HID + c40 * 4];
    const uint32_t sA0 = smem_u32(&As[row0 * PSTRIDE + c40 * 4]);
    const uint32_t sB0 = smem_u32(&Bs[row0 * PSTRIDE + c40 * 4]);
    const uint32_t bufB = TILE_U32 * 4;   // byte offset of buffer 1

    float acc[4][4][4];
    #pragma unroll
    for (int mi = 0; mi < 4; mi++)
        #pragma unroll
        for (int ni = 0; ni < 4; ni++)
            #pragma unroll
            for (int q = 0; q < 4; q++) acc[mi][ni][q] = 0.f;

    // Prefetch tile 0 into buffer 0.
    #pragma unroll
    for (int rep = 0; rep < 4; rep++) {
        CP_ASYNC16(sA0 + rep * SSTEP, gA + rep * GSTEP);
        CP_ASYNC16(sB0 + rep * SSTEP, gB + rep * GSTEP);
    }
    CP_COMMIT();

    int buf = 0;
    const int NT = HID / BK;  // 16
    float bias0[4], bias1[4];
    #pragma unroll 1
    for (int kt = 0; kt < NT; kt++) {
        if (kt + 1 < NT) {
            uint32_t off = (buf ^ 1) ? bufB : 0u;
            const uint32_t kb = (uint32_t)(kt + 1) * BK * 4;  // byte advance
            #pragma unroll
            for (int rep = 0; rep < 4; rep++) {
                CP_ASYNC16(sA0 + off + rep * SSTEP, gA + kb + rep * GSTEP);
                CP_ASYNC16(sB0 + off + rep * SSTEP, gB + kb + rep * GSTEP);
            }
            CP_COMMIT();
            CP_WAIT(1);     // tile kt landed; tile kt+1 may be in flight
        } else {
            CP_WAIT(0);
            // Epilogue bias prefetch: L2 latency overlaps final mma section.
            #pragma unroll
            for (int ni = 0; ni < 4; ni++) {
                int col = n0 + wn + ni * 8 + 2 * tg;
                bias0[ni] = __ldg(&bfc[col]);
                bias1[ni] = __ldg(&bfc[col + 1]);
            }
        }
        __syncthreads();    // tile kt visible to all threads

        const uint32_t* Ab = As + buf * TILE_U32;
        const uint32_t* Bb = Bs + buf * TILE_U32;
        #pragma unroll
        for (int kk = 0; kk < BK; kk += 8) {
            // Permuted layout: physical (kk+2tg, kk+2tg+1) = logical (tg, tg+4).
            uint32_t a[4][4];
            #pragma unroll
            for (int mi = 0; mi < 4; mi++) {
                int r = wm + mi * 16 + g;
                uint2 lo = *(const uint2*)&Ab[r * PSTRIDE + kk + 2 * tg];
                uint2 hi = *(const uint2*)&Ab[(r + 8) * PSTRIDE + kk + 2 * tg];
                a[mi][0] = lo.x; a[mi][2] = lo.y;   // (r,   tg), (r,   tg+4)
                a[mi][1] = hi.x; a[mi][3] = hi.y;   // (r+8, tg), (r+8, tg+4)
            }
            uint32_t bf[4][2];
            #pragma unroll
            for (int ni = 0; ni < 4; ni++) {
                int n = wn + ni * 8 + g;
                uint2 bv = *(const uint2*)&Bb[n * PSTRIDE + kk + 2 * tg];
                bf[ni][0] = bv.x; bf[ni][1] = bv.y; // (n, tg), (n, tg+4)
            }
            #pragma unroll
            for (int mi = 0; mi < 4; mi++)
                #pragma unroll
                for (int ni = 0; ni < 4; ni++)
                    mma_tf32(acc[mi][ni], a[mi], bf[ni]);
        }
        if (kt + 1 < NT) __syncthreads();   // done reading buf before overwrite
        buf ^= 1;
    }

    // Epilogue: + bias (already in regs), float2 stores.
    #pragma unroll
    for (int ni = 0; ni < 4; ni++) {
        int col = n0 + wn + ni * 8 + 2 * tg;
        #pragma unroll
        for (int mi = 0; mi < 4; mi++) {
            int row = m0 + wm + mi * 16 + g;
            float2 v0 = make_float2(acc[mi][ni][0] + bias0[ni],
                                    acc[mi][ni][1] + bias1[ni]);
            float2 v1 = make_float2(acc[mi][ni][2] + bias0[ni],
                                    acc[mi][ni][3] + bias1[ni]);
            *(float2*)&outp[(size_t)row * VOCAB + col] = v0;
            *(float2*)&outp[(size_t)(row + 8) * VOCAB + col] = v1;
        }
    }
}

extern "C" void kernel_launch(void* const* d_in, const int* in_sizes, int n_in,
                              void* d_out, int out_size) {
    const int*   input  = (const int*)d_in[0];
    const float* hidden = (const float*)d_in[1];
    const float* W_ih   = (const float*)d_in[2];
    const float* W_hh   = (const float*)d_in[3];
    const float* b_ih   = (const float*)d_in[4];
    const float* b_hh   = (const float*)d_in[5];
    const float* W_fc   = (const float*)d_in[6];
    const float* b_fc   = (const float*)d_in[7];
    float* outp = (float*)d_out;

    // Idempotent, immediate (not a stream op -> legal under graph capture).
    cudaFuncSetAttribute(proj_kernel,
                         cudaFuncAttributeMaxDynamicSharedMemorySize, PROJ_SMEM);

    // 3 launches total: prep, rnn (h_last folded), proj.
    prep_kernel<<<dim3(VOCAB / 32, HID / 32, 2), dim3(32, 8)>>>(W_ih, W_fc);

    long long logits_elems = (long long)BATCH * TT * VOCAB;
    float* hlast_out = ((long long)out_size >= logits_elems + (long long)BATCH * HID)
                     ? outp + (size_t)out_size - (size_t)BATCH * HID : nullptr;

    rnn_kernel<<<128, 256>>>(input, hidden, W_hh, b_ih, b_hh, hlast_out);

    dim3 grid(VOCAB / BN, (BATCH * TT) / BM);   // n fastest -> W tiles L2-resident
    proj_kernel<<<grid, 256, PROJ_SMEM>>>(b_fc, outp);
}